// round 8
// baseline (speedup 1.0000x reference)
#include <cuda_runtime.h>
#include <cuda_fp16.h>
#include <cuda_bf16.h>
#include <stdint.h>
#include <math.h>

#define NN 30000
#define NE 480000
#define NG 300
#define NDIM 64
#define EDIM 41
#define NCONV 6
#define EPSV 1e-5f
#define KPAD 48

// ---- scratch (static device globals; no runtime allocation) ----
__device__ float g_nf[NN * NDIM];            // node features (7.7 MB)
__device__ float g_P[NN * 256];              // [P1 | P2] per node (30.7 MB, L2-resident)
__device__ __half g_z[(size_t)NE * 128];     // EW, then in-place z (123 MB)
__device__ __nv_bfloat16 g_w3hi[NCONV * 128 * KPAD];
__device__ __nv_bfloat16 g_w3lo[NCONV * 128 * KPAD];
__device__ float g_agg[NN * NDIM];
__device__ float g_stats[256];               // sum[0:128], sumsq[128:256]
__device__ float g_sb[256];                  // BN scale[0:128], bias[128:256]
__device__ float g_gsum[NG * NDIM];
__device__ float g_gcnt[NG];

__device__ __forceinline__ float sp_f(float x) {
    return x > 20.f ? x : log1pf(__expf(x));
}
__device__ __forceinline__ float sig_f(float x) {
    return 1.f / (1.f + __expf(-x));
}

#define MMA_BF16(c0,c1,c2,c3,a0,a1,a2,a3,b0,b1) \
  asm volatile("mma.sync.aligned.m16n8k16.row.col.f32.bf16.bf16.f32 " \
      "{%0,%1,%2,%3}, {%4,%5,%6,%7}, {%8,%9}, {%0,%1,%2,%3};" \
      : "+f"(c0),"+f"(c1),"+f"(c2),"+f"(c3) \
      : "r"(a0),"r"(a1),"r"(a2),"r"(a3),"r"(b0),"r"(b1))

// ---------------- embed: nf = x @ embW + embB ----------------
__global__ void k_embed(const float* __restrict__ x,
                        const float* __restrict__ embW,
                        const float* __restrict__ embB) {
    int c = threadIdx.x;           // 0..63
    float w[92];
#pragma unroll
    for (int k = 0; k < 92; k++) w[k] = embW[k * 64 + c];
    float b = embB[c];

    __shared__ float xs[8][92];
    int v0 = blockIdx.x * 8;
    for (int i = threadIdx.x; i < 8 * 92; i += 64) {
        int n = i / 92, k = i % 92;
        int v = v0 + n;
        xs[n][k] = (v < NN) ? x[v * 92 + k] : 0.f;
    }
    __syncthreads();
#pragma unroll 2
    for (int n = 0; n < 8; n++) {
        int v = v0 + n;
        if (v >= NN) break;
        float acc = b;
#pragma unroll
        for (int k = 0; k < 92; k++) acc += xs[n][k] * w[k];
        g_nf[v * 64 + c] = acc;
    }
}

// ---------------- prep: W3 -> bf16 hi/lo, [l][c][k] ----------------
__global__ void k_prepw(const float* __restrict__ convW) {
    int i = blockIdx.x * 256 + threadIdx.x;
    if (i >= NCONV * 128 * KPAD) return;
    int n = i / KPAD, k = i - n * KPAD;
    int l = n >> 7, c = n & 127;
    float v = (k < EDIM) ? convW[(l * 169 + 128 + k) * 128 + c] : 0.f;
    __nv_bfloat16 h = __float2bfloat16(v);
    g_w3hi[i] = h;
    g_w3lo[i] = __float2bfloat16(v - __bfloat162float(h));
}

// ---------------- launch-level zero ----------------
__global__ void k_zero0() {
    int i = blockIdx.x * blockDim.x + threadIdx.x;
    if (i < NN * NDIM) g_agg[i] = 0.f;
    if (i < 256) g_stats[i] = 0.f;
    if (i < NG * NDIM) g_gsum[i] = 0.f;
    if (i < NG) g_gcnt[i] = 0.f;
}

// ---------------- P = nf @ [W_dst | W_src]  (30000x64 @ 64x256) ----------------
__global__ void k_pgemm(const float* __restrict__ convW, int l) {
    int j = threadIdx.x;  // 0..255
    const float* W = convW + l * 169 * 128;
    float w[64];
#pragma unroll
    for (int d = 0; d < 64; d++)
        w[d] = (j < 128) ? W[d * 128 + j] : W[(64 + d) * 128 + (j - 128)];

    __shared__ float nfs[16][64];
    int v0 = blockIdx.x * 16;
    for (int i = threadIdx.x; i < 16 * 64; i += 256) {
        int n = i / 64, d = i % 64;
        int v = v0 + n;
        nfs[n][d] = (v < NN) ? g_nf[v * 64 + d] : 0.f;
    }
    __syncthreads();
#pragma unroll 2
    for (int n = 0; n < 16; n++) {
        int v = v0 + n;
        if (v >= NN) break;
        float acc = 0.f;
#pragma unroll
        for (int d = 0; d < 64; d++) acc += nfs[n][d] * w[d];
        g_P[v * 256 + j] = acc;
    }
}

// ---------------- EW = ea @ W3_l, block tile M64 x N128 (occupancy-friendly) ----------------
// 256 threads = 8 warps: warp_m = w & 3 (16-row group), warp_n = w >> 2 (64-col half).
// Per-warp tile 16x64 -> acc[32]. Smem 36KB. Writes EW fp16 into g_z.
__global__ void k_ewgemm(const float* __restrict__ ea, int l) {
    __shared__ __nv_bfloat16 Ahi[64 * KPAD], Alo[64 * KPAD];
    __shared__ __nv_bfloat16 Bhi[128 * KPAD], Blo[128 * KPAD];
    int tid = threadIdx.x;
    int m0 = blockIdx.x * 64;

    for (int idx = tid; idx < 64 * KPAD; idx += 256) {
        int r = idx / KPAD, k = idx - r * KPAD;
        float v = (k < EDIM) ? ea[(size_t)(m0 + r) * EDIM + k] : 0.f;
        __nv_bfloat16 h = __float2bfloat16(v);
        Ahi[idx] = h;
        Alo[idx] = __float2bfloat16(v - __bfloat162float(h));
    }
    const __nv_bfloat16* w3h = g_w3hi + l * 128 * KPAD;
    const __nv_bfloat16* w3l = g_w3lo + l * 128 * KPAD;
    for (int idx = tid; idx < 128 * KPAD; idx += 256) {
        Bhi[idx] = w3h[idx];
        Blo[idx] = w3l[idx];
    }
    __syncthreads();

    int w = tid >> 5, lane = tid & 31;
    int wm = w & 3, wn = w >> 2;
    int g = lane >> 2, tq = lane & 3;
    float acc[32];
#pragma unroll
    for (int i = 0; i < 32; i++) acc[i] = 0.f;
    int ar0 = wm * 16 + g;

#pragma unroll
    for (int ks = 0; ks < 3; ks++) {
        int kb = ks * 16 + tq * 2;
        uint32_t ah0 = *(const uint32_t*)&Ahi[ar0 * KPAD + kb];
        uint32_t ah1 = *(const uint32_t*)&Ahi[(ar0 + 8) * KPAD + kb];
        uint32_t ah2 = *(const uint32_t*)&Ahi[ar0 * KPAD + kb + 8];
        uint32_t ah3 = *(const uint32_t*)&Ahi[(ar0 + 8) * KPAD + kb + 8];
        uint32_t al0 = *(const uint32_t*)&Alo[ar0 * KPAD + kb];
        uint32_t al1 = *(const uint32_t*)&Alo[(ar0 + 8) * KPAD + kb];
        uint32_t al2 = *(const uint32_t*)&Alo[ar0 * KPAD + kb + 8];
        uint32_t al3 = *(const uint32_t*)&Alo[(ar0 + 8) * KPAD + kb + 8];
#pragma unroll
        for (int ns = 0; ns < 8; ns++) {
            int bn = wn * 64 + ns * 8 + g;
            uint32_t bh0 = *(const uint32_t*)&Bhi[bn * KPAD + kb];
            uint32_t bh1 = *(const uint32_t*)&Bhi[bn * KPAD + kb + 8];
            uint32_t bl0 = *(const uint32_t*)&Blo[bn * KPAD + kb];
            uint32_t bl1 = *(const uint32_t*)&Blo[bn * KPAD + kb + 8];
            float* c = acc + ns * 4;
            MMA_BF16(c[0], c[1], c[2], c[3], ah0, ah1, ah2, ah3, bh0, bh1);
            MMA_BF16(c[0], c[1], c[2], c[3], ah0, ah1, ah2, ah3, bl0, bl1);
            MMA_BF16(c[0], c[1], c[2], c[3], al0, al1, al2, al3, bh0, bh1);
        }
    }

    size_t row0 = m0 + wm * 16 + g;
#pragma unroll
    for (int ns = 0; ns < 8; ns++) {
        int col = wn * 64 + ns * 8 + tq * 2;
        ((__half2*)g_z)[(row0 * 128 + col) >> 1] =
            __floats2half2_rn(acc[ns * 4 + 0], acc[ns * 4 + 1]);
        ((__half2*)g_z)[((row0 + 8) * 128 + col) >> 1] =
            __floats2half2_rn(acc[ns * 4 + 2], acc[ns * 4 + 3]);
    }
}

// ---------------- statsz: z = EW + P1[dst] + P2[src] (in place, fp16) + BN stats ----------------
// Per-edge accesses are coalesced across the 128 column-threads; P rows are L2-resident.
__global__ void k_statsz(const int* __restrict__ eidx) {
    int tid = threadIdx.x;
    int c = tid & 127, sub = tid >> 7;
    int e0 = blockIdx.x * 256;
    float s = 0.f, sq = 0.f;
#pragma unroll 4
    for (int i = 0; i < 128; i++) {
        int e = e0 + 2 * i + sub;
        int d = eidx[NE + e], sv = eidx[e];
        float z = __half2float(g_z[(size_t)e * 128 + c])
                + g_P[(size_t)d * 256 + c] + g_P[(size_t)sv * 256 + 128 + c];
        g_z[(size_t)e * 128 + c] = __float2half(z);
        s += z; sq += z * z;
    }
    atomicAdd(&g_stats[c], s);
    atomicAdd(&g_stats[128 + c], sq);
}

// ---------------- finalize BN stats -> scale/bias (self-zero stats) ----------------
__global__ void k_stats(const float* __restrict__ bnG,
                        const float* __restrict__ bnB, int l) {
    int c = threadIdx.x;  // 0..127
    float inv = 1.f / (float)NE;
    float mu = g_stats[c] * inv;
    float var = g_stats[128 + c] * inv - mu * mu;
    float sc = rsqrtf(var + EPSV) * bnG[l * 128 + c];
    g_sb[c] = sc;
    g_sb[128 + c] = bnB[l * 128 + c] - mu * sc;
    g_stats[c] = 0.f;
    g_stats[128 + c] = 0.f;
}

// ---------------- apply: read z, BN + gate + scatter-add (no gathers) ----------------
__global__ void k_apply(const int* __restrict__ eidx) {
    __shared__ float sb[256];
    __shared__ int sdst[256];
    int tid = threadIdx.x;
    sb[tid] = g_sb[tid];
    int e0 = blockIdx.x * 256;
    sdst[tid] = eidx[NE + e0 + tid];
    __syncthreads();
    int j = (tid & 31) * 2;   // column pair 0..62
    int es = tid >> 5;        // 0..7
    float sc1a = sb[j],       sc1b = sb[j + 1];
    float bi1a = sb[128 + j], bi1b = sb[129 + j];
    float sc2a = sb[64 + j],  sc2b = sb[65 + j];
    float bi2a = sb[192 + j], bi2b = sb[193 + j];
#pragma unroll 4
    for (int i = 0; i < 32; i++) {
        int er = 8 * i + es;
        size_t e = (size_t)(e0 + er);
        int d = sdst[er];
        __half2 a = *((const __half2*)&g_z[e * 128 + j]);
        __half2 b = *((const __half2*)&g_z[e * 128 + 64 + j]);
        float z1a = __low2float(a) * sc1a + bi1a;
        float z1b = __high2float(a) * sc1b + bi1b;
        float z2a = __low2float(b) * sc2a + bi2a;
        float z2b = __high2float(b) * sc2b + bi2b;
        float ma = sig_f(z1a) * sp_f(z2a);
        float mb = sig_f(z1b) * sp_f(z2b);
        atomicAdd(&g_agg[(size_t)d * 64 + j], ma);
        atomicAdd(&g_agg[(size_t)d * 64 + j + 1], mb);
    }
}

// ---------------- node update: softplus(LN(agg) + nf); self-zero agg ----------------
__global__ void k_node(const float* __restrict__ lnG,
                       const float* __restrict__ lnB, int l) {
    int v = blockIdx.x * 4 + (threadIdx.x >> 5);
    int lane = threadIdx.x & 31;
    if (v >= NN) return;
    float a0 = g_agg[v * 64 + lane];
    float a1 = g_agg[v * 64 + 32 + lane];
    g_agg[v * 64 + lane] = 0.f;
    g_agg[v * 64 + 32 + lane] = 0.f;
    float s = a0 + a1;
    float sq = a0 * a0 + a1 * a1;
#pragma unroll
    for (int o = 16; o > 0; o >>= 1) {
        s  += __shfl_xor_sync(0xffffffff, s, o);
        sq += __shfl_xor_sync(0xffffffff, sq, o);
    }
    float mu = s * (1.f / 64.f);
    float var = sq * (1.f / 64.f) - mu * mu;
    float rs = rsqrtf(var + EPSV);
    float l0 = (a0 - mu) * rs * lnG[l * 64 + lane] + lnB[l * 64 + lane];
    float l1 = (a1 - mu) * rs * lnG[l * 64 + 32 + lane] + lnB[l * 64 + 32 + lane];
    g_nf[v * 64 + lane]      = sp_f(l0 + g_nf[v * 64 + lane]);
    g_nf[v * 64 + 32 + lane] = sp_f(l1 + g_nf[v * 64 + 32 + lane]);
}

// ---------------- pooling ----------------
__global__ void k_pool(const int* __restrict__ batch) {
    int tid = blockIdx.x * blockDim.x + threadIdx.x;
    int v = tid >> 6;
    int c = tid & 63;
    if (v >= NN) return;
    int g = batch[v];
    atomicAdd(&g_gsum[g * 64 + c], g_nf[v * 64 + c]);
    if (c == 0) atomicAdd(&g_gcnt[g], 1.f);
}

// ---------------- final MLP head (300 graphs) ----------------
__global__ void k_mlp(const float* __restrict__ fc1W, const float* __restrict__ fc1B,
                      const float* __restrict__ fcsW, const float* __restrict__ fcsB,
                      const float* __restrict__ foW, const float* __restrict__ foB,
                      float* __restrict__ out) {
    int g = blockIdx.x;
    int c = threadIdx.x;  // 0..127
    __shared__ float s[64];
    __shared__ float h[128];
    __shared__ float red[128];

    if (c < 64) {
        float cnt = g_gcnt[g];
        s[c] = g_gsum[g * 64 + c] / fmaxf(cnt, 1.f);
    }
    __syncthreads();
    float acc = fc1B[c];
#pragma unroll 4
    for (int k = 0; k < 64; k++) acc += s[k] * fc1W[k * 128 + c];
    h[c] = sp_f(acc);
    __syncthreads();
    for (int lh = 0; lh < 3; lh++) {
        float a = fcsB[lh * 128 + c];
#pragma unroll 4
        for (int k = 0; k < 128; k++) a += h[k] * fcsW[(lh * 128 + k) * 128 + c];
        __syncthreads();
        h[c] = sp_f(a);
        __syncthreads();
    }
    red[c] = h[c] * foW[c];
    __syncthreads();
#pragma unroll
    for (int o = 64; o > 0; o >>= 1) {
        if (c < o) red[c] += red[c + o];
        __syncthreads();
    }
    if (c == 0) out[g] = red[0] + foB[0];
}

// ---------------- launch ----------------
extern "C" void kernel_launch(void* const* d_in, const int* in_sizes, int n_in,
                              void* d_out, int out_size) {
    const float* x        = (const float*)d_in[0];
    const float* edge_attr= (const float*)d_in[1];
    const float* embW     = (const float*)d_in[2];
    const float* embB     = (const float*)d_in[3];
    const float* convW    = (const float*)d_in[4];
    const float* bnG      = (const float*)d_in[6];
    const float* bnB      = (const float*)d_in[7];
    const float* lnG      = (const float*)d_in[8];
    const float* lnB      = (const float*)d_in[9];
    const float* fc1W     = (const float*)d_in[10];
    const float* fc1B     = (const float*)d_in[11];
    const float* fcsW     = (const float*)d_in[12];
    const float* fcsB     = (const float*)d_in[13];
    const float* foW      = (const float*)d_in[14];
    const float* foB      = (const float*)d_in[15];
    const int*   eidx     = (const int*)d_in[16];
    const int*   batch    = (const int*)d_in[17];
    float* out = (float*)d_out;

    k_zero0<<<(NN * NDIM + 255) / 256, 256>>>();
    k_embed<<<(NN + 7) / 8, 64>>>(x, embW, embB);
    k_prepw<<<(NCONV * 128 * KPAD + 255) / 256, 256>>>(convW);

    for (int l = 0; l < NCONV; l++) {
        k_pgemm<<<(NN + 15) / 16, 256>>>(convW, l);
        k_ewgemm<<<NE / 64, 256>>>(edge_attr, l);
        k_statsz<<<NE / 256, 256>>>(eidx);
        k_stats<<<1, 128>>>(bnG, bnB, l);
        k_apply<<<NE / 256, 256>>>(eidx);
        k_node<<<(NN + 3) / 4, 128>>>(lnG, lnB, l);
    }

    k_pool<<<(NN * 64 + 255) / 256, 256>>>(batch);
    k_mlp<<<NG, 128>>>(fc1W, fc1B, fcsW, fcsB, foW, foB, out);
}

// round 9
// speedup vs baseline: 1.1288x; 1.1288x over previous
#include <cuda_runtime.h>
#include <cuda_fp16.h>
#include <stdint.h>
#include <math.h>

#define NN 30000
#define NE 480000
#define NG 300
#define NDIM 64
#define EDIM 41
#define NCONV 6
#define EPSV 1e-5f
#define KPAD 48

// ---- scratch (static device globals; no runtime allocation) ----
__device__ float g_nf[NN * NDIM];            // node features (7.7 MB)
__device__ float g_P[NN * 256];              // [P1 | P2] per node (30.7 MB, L2-resident)
__device__ __half g_EW[(size_t)NE * 128];    // per-layer edge GEMM result (123 MB)
__device__ __half g_w3[NCONV * 128 * KPAD];  // W3 fp16, [l][c][k]
__device__ float g_agg[NN * NDIM];
__device__ float g_stats[256];               // sum[0:128], sumsq[128:256]
__device__ float g_sb[256];                  // BN scale[0:128], bias[128:256]
__device__ float g_gsum[NG * NDIM];
__device__ float g_gcnt[NG];

__device__ __forceinline__ float sp_f(float x) {
    return x > 20.f ? x : log1pf(__expf(x));
}
__device__ __forceinline__ float sig_f(float x) {
    return 1.f / (1.f + __expf(-x));
}

#define MMA_F16(c0,c1,c2,c3,a0,a1,a2,a3,b0,b1) \
  asm volatile("mma.sync.aligned.m16n8k16.row.col.f32.f16.f16.f32 " \
      "{%0,%1,%2,%3}, {%4,%5,%6,%7}, {%8,%9}, {%0,%1,%2,%3};" \
      : "+f"(c0),"+f"(c1),"+f"(c2),"+f"(c3) \
      : "r"(a0),"r"(a1),"r"(a2),"r"(a3),"r"(b0),"r"(b1))

// ---------------- embed: nf = x @ embW + embB ----------------
__global__ void k_embed(const float* __restrict__ x,
                        const float* __restrict__ embW,
                        const float* __restrict__ embB) {
    int c = threadIdx.x;           // 0..63
    float w[92];
#pragma unroll
    for (int k = 0; k < 92; k++) w[k] = embW[k * 64 + c];
    float b = embB[c];

    __shared__ float xs[8][92];
    int v0 = blockIdx.x * 8;
    for (int i = threadIdx.x; i < 8 * 92; i += 64) {
        int n = i / 92, k = i % 92;
        int v = v0 + n;
        xs[n][k] = (v < NN) ? x[v * 92 + k] : 0.f;
    }
    __syncthreads();
#pragma unroll 2
    for (int n = 0; n < 8; n++) {
        int v = v0 + n;
        if (v >= NN) break;
        float acc = b;
#pragma unroll
        for (int k = 0; k < 92; k++) acc += xs[n][k] * w[k];
        g_nf[v * 64 + c] = acc;
    }
}

// ---------------- prep: W3 (rows 128..168 of conv weights) -> fp16, [l][c][k] ----------------
__global__ void k_prepw(const float* __restrict__ convW) {
    int i = blockIdx.x * 256 + threadIdx.x;
    if (i >= NCONV * 128 * KPAD) return;
    int n = i / KPAD, k = i - n * KPAD;
    int l = n >> 7, c = n & 127;
    float v = (k < EDIM) ? convW[(l * 169 + 128 + k) * 128 + c] : 0.f;
    g_w3[i] = __float2half(v);
}

// ---------------- launch-level zero ----------------
__global__ void k_zero0() {
    int i = blockIdx.x * blockDim.x + threadIdx.x;
    if (i < NN * NDIM) g_agg[i] = 0.f;
    if (i < 256) g_stats[i] = 0.f;
    if (i < NG * NDIM) g_gsum[i] = 0.f;
    if (i < NG) g_gcnt[i] = 0.f;
}

// ---------------- P = nf @ [W_dst | W_src]  (30000x64 @ 64x256) ----------------
__global__ void k_pgemm(const float* __restrict__ convW, int l) {
    int j = threadIdx.x;  // 0..255
    const float* W = convW + l * 169 * 128;
    float w[64];
#pragma unroll
    for (int d = 0; d < 64; d++)
        w[d] = (j < 128) ? W[d * 128 + j] : W[(64 + d) * 128 + (j - 128)];

    __shared__ float nfs[16][64];
    int v0 = blockIdx.x * 16;
    for (int i = threadIdx.x; i < 16 * 64; i += 256) {
        int n = i / 64, d = i % 64;
        int v = v0 + n;
        nfs[n][d] = (v < NN) ? g_nf[v * 64 + d] : 0.f;
    }
    __syncthreads();
#pragma unroll 2
    for (int n = 0; n < 16; n++) {
        int v = v0 + n;
        if (v >= NN) break;
        float acc = 0.f;
#pragma unroll
        for (int d = 0; d < 64; d++) acc += nfs[n][d] * w[d];
        g_P[v * 256 + j] = acc;
    }
}

// ---------------- EW = ea @ W3_l  (fp16 single-product mma, M64 x N128 tile) ----------------
// 256 threads = 8 warps: wm = w & 3 (16-row group), wn = w >> 2 (64-col half).
// Per-warp tile 16x64 -> acc[32]. Smem 18KB -> ~3 CTAs/SM.
__global__ void k_ewgemm16(const float* __restrict__ ea, int l) {
    __shared__ __half Ah[64 * KPAD];
    __shared__ __half Bh[128 * KPAD];
    int tid = threadIdx.x;
    int m0 = blockIdx.x * 64;

    for (int idx = tid; idx < 64 * KPAD; idx += 256) {
        int r = idx / KPAD, k = idx - r * KPAD;
        float v = (k < EDIM) ? ea[(size_t)(m0 + r) * EDIM + k] : 0.f;
        Ah[idx] = __float2half(v);
    }
    const __half* w3 = g_w3 + l * 128 * KPAD;
    for (int idx = tid; idx < 128 * KPAD; idx += 256) {
        Bh[idx] = w3[idx];
    }
    __syncthreads();

    int w = tid >> 5, lane = tid & 31;
    int wm = w & 3, wn = w >> 2;
    int g = lane >> 2, tq = lane & 3;
    float acc[32];
#pragma unroll
    for (int i = 0; i < 32; i++) acc[i] = 0.f;
    int ar0 = wm * 16 + g;

#pragma unroll
    for (int ks = 0; ks < 3; ks++) {
        int kb = ks * 16 + tq * 2;
        uint32_t a0 = *(const uint32_t*)&Ah[ar0 * KPAD + kb];
        uint32_t a1 = *(const uint32_t*)&Ah[(ar0 + 8) * KPAD + kb];
        uint32_t a2 = *(const uint32_t*)&Ah[ar0 * KPAD + kb + 8];
        uint32_t a3 = *(const uint32_t*)&Ah[(ar0 + 8) * KPAD + kb + 8];
#pragma unroll
        for (int ns = 0; ns < 8; ns++) {
            int bn = wn * 64 + ns * 8 + g;
            uint32_t b0 = *(const uint32_t*)&Bh[bn * KPAD + kb];
            uint32_t b1 = *(const uint32_t*)&Bh[bn * KPAD + kb + 8];
            float* c = acc + ns * 4;
            MMA_F16(c[0], c[1], c[2], c[3], a0, a1, a2, a3, b0, b1);
        }
    }

    size_t row0 = m0 + wm * 16 + g;
#pragma unroll
    for (int ns = 0; ns < 8; ns++) {
        int col = wn * 64 + ns * 8 + tq * 2;
        ((__half2*)g_EW)[(row0 * 128 + col) >> 1] =
            __floats2half2_rn(acc[ns * 4 + 0], acc[ns * 4 + 1]);
        ((__half2*)g_EW)[((row0 + 8) * 128 + col) >> 1] =
            __floats2half2_rn(acc[ns * 4 + 2], acc[ns * 4 + 3]);
    }
}

// ---------------- pass A: BN statistics only (z recomputed, never stored) ----------------
// Conv bias cancels in BatchNorm (constant shift drops out of z - mu).
__global__ void k_statsA(const int* __restrict__ eidx) {
    int tid = threadIdx.x;
    int c = tid & 127, sub = tid >> 7;
    int e0 = blockIdx.x * 256;
    float s = 0.f, sq = 0.f;
#pragma unroll 4
    for (int i = 0; i < 128; i++) {
        int e = e0 + 2 * i + sub;
        int d = eidx[NE + e], sv = eidx[e];
        float z = __half2float(g_EW[(size_t)e * 128 + c])
                + g_P[(size_t)d * 256 + c] + g_P[(size_t)sv * 256 + 128 + c];
        s += z; sq += z * z;
    }
    atomicAdd(&g_stats[c], s);
    atomicAdd(&g_stats[128 + c], sq);
}

// ---------------- finalize BN stats -> scale/bias (self-zero stats) ----------------
__global__ void k_stats(const float* __restrict__ bnG,
                        const float* __restrict__ bnB, int l) {
    int c = threadIdx.x;  // 0..127
    float inv = 1.f / (float)NE;
    float mu = g_stats[c] * inv;
    float var = g_stats[128 + c] * inv - mu * mu;
    float sc = rsqrtf(var + EPSV) * bnG[l * 128 + c];
    g_sb[c] = sc;
    g_sb[128 + c] = bnB[l * 128 + c] - mu * sc;
    g_stats[c] = 0.f;
    g_stats[128 + c] = 0.f;
}

// ---------------- apply: recompute z, BN + gate + scatter-add ----------------
__global__ void k_apply(const int* __restrict__ eidx) {
    __shared__ float sb[256];
    int tid = threadIdx.x;
    sb[tid] = g_sb[tid];
    __syncthreads();
    int cb = tid & 63, es = tid >> 6;
    int e0 = blockIdx.x * 256;
    float sc1 = sb[cb],       bi1 = sb[128 + cb];
    float sc2 = sb[64 + cb],  bi2 = sb[192 + cb];
#pragma unroll 2
    for (int i = 0; i < 64; i++) {
        int e = e0 + 4 * i + es;
        int d = eidx[NE + e], sv = eidx[e];
        float z1 = __half2float(g_EW[(size_t)e * 128 + cb])
                 + g_P[(size_t)d * 256 + cb] + g_P[(size_t)sv * 256 + 128 + cb];
        float z2 = __half2float(g_EW[(size_t)e * 128 + 64 + cb])
                 + g_P[(size_t)d * 256 + 64 + cb] + g_P[(size_t)sv * 256 + 192 + cb];
        z1 = z1 * sc1 + bi1;
        z2 = z2 * sc2 + bi2;
        float m = sig_f(z1) * sp_f(z2);
        atomicAdd(&g_agg[(size_t)d * 64 + cb], m);
    }
}

// ---------------- node update: softplus(LN(agg) + nf); self-zero agg ----------------
__global__ void k_node(const float* __restrict__ lnG,
                       const float* __restrict__ lnB, int l) {
    int v = blockIdx.x * 4 + (threadIdx.x >> 5);
    int lane = threadIdx.x & 31;
    if (v >= NN) return;
    float a0 = g_agg[v * 64 + lane];
    float a1 = g_agg[v * 64 + 32 + lane];
    g_agg[v * 64 + lane] = 0.f;
    g_agg[v * 64 + 32 + lane] = 0.f;
    float s = a0 + a1;
    float sq = a0 * a0 + a1 * a1;
#pragma unroll
    for (int o = 16; o > 0; o >>= 1) {
        s  += __shfl_xor_sync(0xffffffff, s, o);
        sq += __shfl_xor_sync(0xffffffff, sq, o);
    }
    float mu = s * (1.f / 64.f);
    float var = sq * (1.f / 64.f) - mu * mu;
    float rs = rsqrtf(var + EPSV);
    float l0 = (a0 - mu) * rs * lnG[l * 64 + lane] + lnB[l * 64 + lane];
    float l1 = (a1 - mu) * rs * lnG[l * 64 + 32 + lane] + lnB[l * 64 + 32 + lane];
    g_nf[v * 64 + lane]      = sp_f(l0 + g_nf[v * 64 + lane]);
    g_nf[v * 64 + 32 + lane] = sp_f(l1 + g_nf[v * 64 + 32 + lane]);
}

// ---------------- pooling ----------------
__global__ void k_pool(const int* __restrict__ batch) {
    int tid = blockIdx.x * blockDim.x + threadIdx.x;
    int v = tid >> 6;
    int c = tid & 63;
    if (v >= NN) return;
    int g = batch[v];
    atomicAdd(&g_gsum[g * 64 + c], g_nf[v * 64 + c]);
    if (c == 0) atomicAdd(&g_gcnt[g], 1.f);
}

// ---------------- final MLP head (300 graphs) ----------------
__global__ void k_mlp(const float* __restrict__ fc1W, const float* __restrict__ fc1B,
                      const float* __restrict__ fcsW, const float* __restrict__ fcsB,
                      const float* __restrict__ foW, const float* __restrict__ foB,
                      float* __restrict__ out) {
    int g = blockIdx.x;
    int c = threadIdx.x;  // 0..127
    __shared__ float s[64];
    __shared__ float h[128];
    __shared__ float red[128];

    if (c < 64) {
        float cnt = g_gcnt[g];
        s[c] = g_gsum[g * 64 + c] / fmaxf(cnt, 1.f);
    }
    __syncthreads();
    float acc = fc1B[c];
#pragma unroll 4
    for (int k = 0; k < 64; k++) acc += s[k] * fc1W[k * 128 + c];
    h[c] = sp_f(acc);
    __syncthreads();
    for (int lh = 0; lh < 3; lh++) {
        float a = fcsB[lh * 128 + c];
#pragma unroll 4
        for (int k = 0; k < 128; k++) a += h[k] * fcsW[(lh * 128 + k) * 128 + c];
        __syncthreads();
        h[c] = sp_f(a);
        __syncthreads();
    }
    red[c] = h[c] * foW[c];
    __syncthreads();
#pragma unroll
    for (int o = 64; o > 0; o >>= 1) {
        if (c < o) red[c] += red[c + o];
        __syncthreads();
    }
    if (c == 0) out[g] = red[0] + foB[0];
}

// ---------------- launch ----------------
extern "C" void kernel_launch(void* const* d_in, const int* in_sizes, int n_in,
                              void* d_out, int out_size) {
    const float* x        = (const float*)d_in[0];
    const float* edge_attr= (const float*)d_in[1];
    const float* embW     = (const float*)d_in[2];
    const float* embB     = (const float*)d_in[3];
    const float* convW    = (const float*)d_in[4];
    const float* bnG      = (const float*)d_in[6];
    const float* bnB      = (const float*)d_in[7];
    const float* lnG      = (const float*)d_in[8];
    const float* lnB      = (const float*)d_in[9];
    const float* fc1W     = (const float*)d_in[10];
    const float* fc1B     = (const float*)d_in[11];
    const float* fcsW     = (const float*)d_in[12];
    const float* fcsB     = (const float*)d_in[13];
    const float* foW      = (const float*)d_in[14];
    const float* foB      = (const float*)d_in[15];
    const int*   eidx     = (const int*)d_in[16];
    const int*   batch    = (const int*)d_in[17];
    float* out = (float*)d_out;

    k_zero0<<<(NN * NDIM + 255) / 256, 256>>>();
    k_embed<<<(NN + 7) / 8, 64>>>(x, embW, embB);
    k_prepw<<<(NCONV * 128 * KPAD + 255) / 256, 256>>>(convW);

    for (int l = 0; l < NCONV; l++) {
        k_pgemm<<<(NN + 15) / 16, 256>>>(convW, l);
        k_ewgemm16<<<NE / 64, 256>>>(edge_attr, l);
        k_statsA<<<NE / 256, 256>>>(eidx);
        k_stats<<<1, 128>>>(bnG, bnB, l);
        k_apply<<<NE / 256, 256>>>(eidx);
        k_node<<<(NN + 3) / 4, 128>>>(lnG, lnB, l);
    }

    k_pool<<<(NN * 64 + 255) / 256, 256>>>(batch);
    k_mlp<<<NG, 128>>>(fc1W, fc1B, fcsW, fcsB, foW, foB, out);
}

// round 10
// speedup vs baseline: 1.1855x; 1.0502x over previous
#include <cuda_runtime.h>
#include <cuda_fp16.h>
#include <stdint.h>
#include <math.h>

#define NN 30000
#define NE 480000
#define NG 300
#define NDIM 64
#define EDIM 41
#define NCONV 6
#define EPSV 1e-5f
#define KPAD 48

// ---- scratch (static device globals; no runtime allocation) ----
__device__ float g_nf[NN * NDIM];            // node features (7.7 MB)
__device__ float g_P[NN * 256];              // [P1 | P2] per node (30.7 MB, L2-resident)
__device__ __half g_z[(size_t)NE * 128];     // per-layer pre-BN z (123 MB)
__device__ __half g_w3[NCONV * 128 * KPAD];  // W3 fp16, [l][c][k]
__device__ float g_agg[NN * NDIM];
__device__ float g_stats[256];               // sum[0:128], sumsq[128:256]
__device__ float g_sb[256];                  // BN scale[0:128], bias[128:256]
__device__ float g_gsum[NG * NDIM];
__device__ float g_gcnt[NG];

__device__ __forceinline__ float sp_f(float x) {
    return x > 20.f ? x : log1pf(__expf(x));
}
__device__ __forceinline__ float sig_f(float x) {
    return 1.f / (1.f + __expf(-x));
}

#define MMA_F16(c0,c1,c2,c3,a0,a1,a2,a3,b0,b1) \
  asm volatile("mma.sync.aligned.m16n8k16.row.col.f32.f16.f16.f32 " \
      "{%0,%1,%2,%3}, {%4,%5,%6,%7}, {%8,%9}, {%0,%1,%2,%3};" \
      : "+f"(c0),"+f"(c1),"+f"(c2),"+f"(c3) \
      : "r"(a0),"r"(a1),"r"(a2),"r"(a3),"r"(b0),"r"(b1))

// ---------------- embed: nf = x @ embW + embB ----------------
__global__ void k_embed(const float* __restrict__ x,
                        const float* __restrict__ embW,
                        const float* __restrict__ embB) {
    int c = threadIdx.x;           // 0..63
    float w[92];
#pragma unroll
    for (int k = 0; k < 92; k++) w[k] = embW[k * 64 + c];
    float b = embB[c];

    __shared__ float xs[8][92];
    int v0 = blockIdx.x * 8;
    for (int i = threadIdx.x; i < 8 * 92; i += 64) {
        int n = i / 92, k = i % 92;
        int v = v0 + n;
        xs[n][k] = (v < NN) ? x[v * 92 + k] : 0.f;
    }
    __syncthreads();
#pragma unroll 2
    for (int n = 0; n < 8; n++) {
        int v = v0 + n;
        if (v >= NN) break;
        float acc = b;
#pragma unroll
        for (int k = 0; k < 92; k++) acc += xs[n][k] * w[k];
        g_nf[v * 64 + c] = acc;
    }
}

// ---------------- prep: W3 (rows 128..168 of conv weights) -> fp16, [l][c][k] ----------------
__global__ void k_prepw(const float* __restrict__ convW) {
    int i = blockIdx.x * 256 + threadIdx.x;
    if (i >= NCONV * 128 * KPAD) return;
    int n = i / KPAD, k = i - n * KPAD;
    int l = n >> 7, c = n & 127;
    float v = (k < EDIM) ? convW[(l * 169 + 128 + k) * 128 + c] : 0.f;
    g_w3[i] = __float2half(v);
}

// ---------------- launch-level zero ----------------
__global__ void k_zero0() {
    int i = blockIdx.x * blockDim.x + threadIdx.x;
    if (i < NN * NDIM) g_agg[i] = 0.f;
    if (i < 256) g_stats[i] = 0.f;
    if (i < NG * NDIM) g_gsum[i] = 0.f;
    if (i < NG) g_gcnt[i] = 0.f;
}

// ---------------- P = nf @ [W_dst | W_src]  (30000x64 @ 64x256) ----------------
__global__ void k_pgemm(const float* __restrict__ convW, int l) {
    int j = threadIdx.x;  // 0..255
    const float* W = convW + l * 169 * 128;
    float w[64];
#pragma unroll
    for (int d = 0; d < 64; d++)
        w[d] = (j < 128) ? W[d * 128 + j] : W[(64 + d) * 128 + (j - 128)];

    __shared__ float nfs[16][64];
    int v0 = blockIdx.x * 16;
    for (int i = threadIdx.x; i < 16 * 64; i += 256) {
        int n = i / 64, d = i % 64;
        int v = v0 + n;
        nfs[n][d] = (v < NN) ? g_nf[v * 64 + d] : 0.f;
    }
    __syncthreads();
#pragma unroll 2
    for (int n = 0; n < 16; n++) {
        int v = v0 + n;
        if (v >= NN) break;
        float acc = 0.f;
#pragma unroll
        for (int d = 0; d < 64; d++) acc += nfs[n][d] * w[d];
        g_P[v * 256 + j] = acc;
    }
}

// ---------------- fused: z = ea@W3 + P1[dst] + P2[src] (fp16 mma) + z store + BN stats ----------------
// Tile M64 x N128, 256 threads (8 warps): wm = w & 3, wn = w >> 2. Smem 19KB.
// Conv bias cancels in BatchNorm.
__global__ void k_ewfused16(const float* __restrict__ ea,
                            const int* __restrict__ eidx, int l) {
    __shared__ __half Ah[64 * KPAD];
    __shared__ __half Bh[128 * KPAD];
    __shared__ float sred[256];
    int tid = threadIdx.x;
    int m0 = blockIdx.x * 64;

    sred[tid] = 0.f;
    for (int idx = tid; idx < 64 * KPAD; idx += 256) {
        int r = idx / KPAD, k = idx - r * KPAD;
        float v = (k < EDIM) ? ea[(size_t)(m0 + r) * EDIM + k] : 0.f;
        Ah[idx] = __float2half(v);
    }
    const __half* w3 = g_w3 + l * 128 * KPAD;
    for (int idx = tid; idx < 128 * KPAD; idx += 256) {
        Bh[idx] = w3[idx];
    }
    __syncthreads();

    int w = tid >> 5, lane = tid & 31;
    int wm = w & 3, wn = w >> 2;
    int g = lane >> 2, tq = lane & 3;
    float acc[32];
#pragma unroll
    for (int i = 0; i < 32; i++) acc[i] = 0.f;
    int ar0 = wm * 16 + g;

#pragma unroll
    for (int ks = 0; ks < 3; ks++) {
        int kb = ks * 16 + tq * 2;
        uint32_t a0 = *(const uint32_t*)&Ah[ar0 * KPAD + kb];
        uint32_t a1 = *(const uint32_t*)&Ah[(ar0 + 8) * KPAD + kb];
        uint32_t a2 = *(const uint32_t*)&Ah[ar0 * KPAD + kb + 8];
        uint32_t a3 = *(const uint32_t*)&Ah[(ar0 + 8) * KPAD + kb + 8];
#pragma unroll
        for (int ns = 0; ns < 8; ns++) {
            int bn = wn * 64 + ns * 8 + g;
            uint32_t b0 = *(const uint32_t*)&Bh[bn * KPAD + kb];
            uint32_t b1 = *(const uint32_t*)&Bh[bn * KPAD + kb + 8];
            float* c = acc + ns * 4;
            MMA_F16(c[0], c[1], c[2], c[3], a0, a1, a2, a3, b0, b1);
        }
    }

    // ---- epilogue: gather P (L2-resident), write z fp16, reduce BN stats ----
    int r0 = wm * 16 + g, r1 = r0 + 8;
    int d0 = eidx[NE + m0 + r0], s0 = eidx[m0 + r0];
    int d1 = eidx[NE + m0 + r1], s1 = eidx[m0 + r1];
#pragma unroll
    for (int ns = 0; ns < 8; ns++) {
        int col = wn * 64 + ns * 8 + tq * 2;
        float2 pd0 = *(const float2*)&g_P[(size_t)d0 * 256 + col];
        float2 ps0 = *(const float2*)&g_P[(size_t)s0 * 256 + 128 + col];
        float2 pd1 = *(const float2*)&g_P[(size_t)d1 * 256 + col];
        float2 ps1 = *(const float2*)&g_P[(size_t)s1 * 256 + 128 + col];
        float z00 = acc[ns * 4 + 0] + pd0.x + ps0.x;
        float z01 = acc[ns * 4 + 1] + pd0.y + ps0.y;
        float z10 = acc[ns * 4 + 2] + pd1.x + ps1.x;
        float z11 = acc[ns * 4 + 3] + pd1.y + ps1.y;
        ((__half2*)g_z)[((size_t)(m0 + r0) * 128 + col) >> 1] = __floats2half2_rn(z00, z01);
        ((__half2*)g_z)[((size_t)(m0 + r1) * 128 + col) >> 1] = __floats2half2_rn(z10, z11);
        acc[ns * 4 + 0] = z00 + z10;
        acc[ns * 4 + 1] = z01 + z11;
        acc[ns * 4 + 2] = z00 * z00 + z10 * z10;
        acc[ns * 4 + 3] = z01 * z01 + z11 * z11;
    }
    // reduce across g (lane bits 2..4); tq preserved
#pragma unroll
    for (int off = 4; off <= 16; off <<= 1) {
#pragma unroll
        for (int i = 0; i < 32; i++)
            acc[i] += __shfl_xor_sync(0xffffffff, acc[i], off);
    }
    if (g == 0) {
#pragma unroll
        for (int ns = 0; ns < 8; ns++) {
            int col = wn * 64 + ns * 8 + tq * 2;
            atomicAdd(&sred[col],           acc[ns * 4 + 0]);
            atomicAdd(&sred[col + 1],       acc[ns * 4 + 1]);
            atomicAdd(&sred[128 + col],     acc[ns * 4 + 2]);
            atomicAdd(&sred[129 + col],     acc[ns * 4 + 3]);
        }
    }
    __syncthreads();
    atomicAdd(&g_stats[tid], sred[tid]);
}

// ---------------- finalize BN stats -> scale/bias (self-zero stats) ----------------
__global__ void k_stats(const float* __restrict__ bnG,
                        const float* __restrict__ bnB, int l) {
    int c = threadIdx.x;  // 0..127
    float inv = 1.f / (float)NE;
    float mu = g_stats[c] * inv;
    float var = g_stats[128 + c] * inv - mu * mu;
    float sc = rsqrtf(var + EPSV) * bnG[l * 128 + c];
    g_sb[c] = sc;
    g_sb[128 + c] = bnB[l * 128 + c] - mu * sc;
    g_stats[c] = 0.f;
    g_stats[128 + c] = 0.f;
}

// ---------------- apply: read z, BN + gate + scatter-add (no gathers) ----------------
__global__ void k_apply(const int* __restrict__ eidx) {
    __shared__ float sb[256];
    __shared__ int sdst[256];
    int tid = threadIdx.x;
    sb[tid] = g_sb[tid];
    int e0 = blockIdx.x * 256;
    sdst[tid] = eidx[NE + e0 + tid];
    __syncthreads();
    int j = (tid & 31) * 2;   // column pair 0..62
    int es = tid >> 5;        // 0..7
    float sc1a = sb[j],       sc1b = sb[j + 1];
    float bi1a = sb[128 + j], bi1b = sb[129 + j];
    float sc2a = sb[64 + j],  sc2b = sb[65 + j];
    float bi2a = sb[192 + j], bi2b = sb[193 + j];
#pragma unroll 4
    for (int i = 0; i < 32; i++) {
        int er = 8 * i + es;
        size_t e = (size_t)(e0 + er);
        int d = sdst[er];
        __half2 a = *((const __half2*)&g_z[e * 128 + j]);
        __half2 b = *((const __half2*)&g_z[e * 128 + 64 + j]);
        float z1a = __low2float(a) * sc1a + bi1a;
        float z1b = __high2float(a) * sc1b + bi1b;
        float z2a = __low2float(b) * sc2a + bi2a;
        float z2b = __high2float(b) * sc2b + bi2b;
        float ma = sig_f(z1a) * sp_f(z2a);
        float mb = sig_f(z1b) * sp_f(z2b);
        atomicAdd(&g_agg[(size_t)d * 64 + j], ma);
        atomicAdd(&g_agg[(size_t)d * 64 + j + 1], mb);
    }
}

// ---------------- node update: softplus(LN(agg) + nf); self-zero agg ----------------
__global__ void k_node(const float* __restrict__ lnG,
                       const float* __restrict__ lnB, int l) {
    int v = blockIdx.x * 4 + (threadIdx.x >> 5);
    int lane = threadIdx.x & 31;
    if (v >= NN) return;
    float a0 = g_agg[v * 64 + lane];
    float a1 = g_agg[v * 64 + 32 + lane];
    g_agg[v * 64 + lane] = 0.f;
    g_agg[v * 64 + 32 + lane] = 0.f;
    float s = a0 + a1;
    float sq = a0 * a0 + a1 * a1;
#pragma unroll
    for (int o = 16; o > 0; o >>= 1) {
        s  += __shfl_xor_sync(0xffffffff, s, o);
        sq += __shfl_xor_sync(0xffffffff, sq, o);
    }
    float mu = s * (1.f / 64.f);
    float var = sq * (1.f / 64.f) - mu * mu;
    float rs = rsqrtf(var + EPSV);
    float l0 = (a0 - mu) * rs * lnG[l * 64 + lane] + lnB[l * 64 + lane];
    float l1 = (a1 - mu) * rs * lnG[l * 64 + 32 + lane] + lnB[l * 64 + 32 + lane];
    g_nf[v * 64 + lane]      = sp_f(l0 + g_nf[v * 64 + lane]);
    g_nf[v * 64 + 32 + lane] = sp_f(l1 + g_nf[v * 64 + 32 + lane]);
}

// ---------------- pooling ----------------
__global__ void k_pool(const int* __restrict__ batch) {
    int tid = blockIdx.x * blockDim.x + threadIdx.x;
    int v = tid >> 6;
    int c = tid & 63;
    if (v >= NN) return;
    int g = batch[v];
    atomicAdd(&g_gsum[g * 64 + c], g_nf[v * 64 + c]);
    if (c == 0) atomicAdd(&g_gcnt[g], 1.f);
}

// ---------------- final MLP head (300 graphs) ----------------
__global__ void k_mlp(const float* __restrict__ fc1W, const float* __restrict__ fc1B,
                      const float* __restrict__ fcsW, const float* __restrict__ fcsB,
                      const float* __restrict__ foW, const float* __restrict__ foB,
                      float* __restrict__ out) {
    int g = blockIdx.x;
    int c = threadIdx.x;  // 0..127
    __shared__ float s[64];
    __shared__ float h[128];
    __shared__ float red[128];

    if (c < 64) {
        float cnt = g_gcnt[g];
        s[c] = g_gsum[g * 64 + c] / fmaxf(cnt, 1.f);
    }
    __syncthreads();
    float acc = fc1B[c];
#pragma unroll 4
    for (int k = 0; k < 64; k++) acc += s[k] * fc1W[k * 128 + c];
    h[c] = sp_f(acc);
    __syncthreads();
    for (int lh = 0; lh < 3; lh++) {
        float a = fcsB[lh * 128 + c];
#pragma unroll 4
        for (int k = 0; k < 128; k++) a += h[k] * fcsW[(lh * 128 + k) * 128 + c];
        __syncthreads();
        h[c] = sp_f(a);
        __syncthreads();
    }
    red[c] = h[c] * foW[c];
    __syncthreads();
#pragma unroll
    for (int o = 64; o > 0; o >>= 1) {
        if (c < o) red[c] += red[c + o];
        __syncthreads();
    }
    if (c == 0) out[g] = red[0] + foB[0];
}

// ---------------- launch ----------------
extern "C" void kernel_launch(void* const* d_in, const int* in_sizes, int n_in,
                              void* d_out, int out_size) {
    const float* x        = (const float*)d_in[0];
    const float* edge_attr= (const float*)d_in[1];
    const float* embW     = (const float*)d_in[2];
    const float* embB     = (const float*)d_in[3];
    const float* convW    = (const float*)d_in[4];
    const float* bnG      = (const float*)d_in[6];
    const float* bnB      = (const float*)d_in[7];
    const float* lnG      = (const float*)d_in[8];
    const float* lnB      = (const float*)d_in[9];
    const float* fc1W     = (const float*)d_in[10];
    const float* fc1B     = (const float*)d_in[11];
    const float* fcsW     = (const float*)d_in[12];
    const float* fcsB     = (const float*)d_in[13];
    const float* foW      = (const float*)d_in[14];
    const float* foB      = (const float*)d_in[15];
    const int*   eidx     = (const int*)d_in[16];
    const int*   batch    = (const int*)d_in[17];
    float* out = (float*)d_out;

    k_zero0<<<(NN * NDIM + 255) / 256, 256>>>();
    k_embed<<<(NN + 7) / 8, 64>>>(x, embW, embB);
    k_prepw<<<(NCONV * 128 * KPAD + 255) / 256, 256>>>(convW);

    for (int l = 0; l < NCONV; l++) {
        k_pgemm<<<(NN + 15) / 16, 256>>>(convW, l);
        k_ewfused16<<<NE / 64, 256>>>(edge_attr, eidx, l);
        k_stats<<<1, 128>>>(bnG, bnB, l);
        k_apply<<<NE / 256, 256>>>(eidx);
        k_node<<<(NN + 3) / 4, 128>>>(lnG, lnB, l);
    }

    k_pool<<<(NN * 64 + 255) / 256, 256>>>(batch);
    k_mlp<<<NG, 128>>>(fc1W, fc1B, fcsW, fcsB, foW, foB, out);
}

// round 11
// speedup vs baseline: 1.2422x; 1.0478x over previous
#include <cuda_runtime.h>
#include <cuda_fp16.h>
#include <stdint.h>
#include <math.h>

#define NN 30000
#define NE 480000
#define NG 300
#define NDIM 64
#define EDIM 41
#define NCONV 6
#define EPSV 1e-5f
#define KPAD 48
#define KP2 72   // pgemm16 K padding (K=64 -> 72 to avoid 128B-stride bank conflicts)

// ---- scratch (static device globals; no runtime allocation) ----
__device__ float g_nf[NN * NDIM];            // node features fp32 (7.7 MB)
__device__ __half g_P[NN * 256];             // [P1 | P2] per node, fp16 (15.4 MB, L2-resident)
__device__ __half g_z[(size_t)NE * 128];     // per-layer pre-BN z (123 MB)
__device__ __half g_w3[NCONV * 128 * KPAD];  // W3 fp16, [l][c][k]
__device__ float g_agg[NN * NDIM];
__device__ float g_stats[256];               // sum[0:128], sumsq[128:256]
__device__ float g_sb[256];                  // BN scale[0:128], bias[128:256]
__device__ float g_gsum[NG * NDIM];
__device__ float g_gcnt[NG];

__device__ __forceinline__ float sp_f(float x) {
    return x > 20.f ? x : log1pf(__expf(x));
}
__device__ __forceinline__ float sig_f(float x) {
    return 1.f / (1.f + __expf(-x));
}

#define MMA_F16(c0,c1,c2,c3,a0,a1,a2,a3,b0,b1) \
  asm volatile("mma.sync.aligned.m16n8k16.row.col.f32.f16.f16.f32 " \
      "{%0,%1,%2,%3}, {%4,%5,%6,%7}, {%8,%9}, {%0,%1,%2,%3};" \
      : "+f"(c0),"+f"(c1),"+f"(c2),"+f"(c3) \
      : "r"(a0),"r"(a1),"r"(a2),"r"(a3),"r"(b0),"r"(b1))

// ---------------- embed: nf = x @ embW + embB ----------------
__global__ void k_embed(const float* __restrict__ x,
                        const float* __restrict__ embW,
                        const float* __restrict__ embB) {
    int c = threadIdx.x;           // 0..63
    float w[92];
#pragma unroll
    for (int k = 0; k < 92; k++) w[k] = embW[k * 64 + c];
    float b = embB[c];

    __shared__ float xs[8][92];
    int v0 = blockIdx.x * 8;
    for (int i = threadIdx.x; i < 8 * 92; i += 64) {
        int n = i / 92, k = i % 92;
        int v = v0 + n;
        xs[n][k] = (v < NN) ? x[v * 92 + k] : 0.f;
    }
    __syncthreads();
#pragma unroll 2
    for (int n = 0; n < 8; n++) {
        int v = v0 + n;
        if (v >= NN) break;
        float acc = b;
#pragma unroll
        for (int k = 0; k < 92; k++) acc += xs[n][k] * w[k];
        g_nf[v * 64 + c] = acc;
    }
}

// ---------------- prep: W3 (rows 128..168 of conv weights) -> fp16, [l][c][k] ----------------
__global__ void k_prepw(const float* __restrict__ convW) {
    int i = blockIdx.x * 256 + threadIdx.x;
    if (i >= NCONV * 128 * KPAD) return;
    int n = i / KPAD, k = i - n * KPAD;
    int l = n >> 7, c = n & 127;
    float v = (k < EDIM) ? convW[(l * 169 + 128 + k) * 128 + c] : 0.f;
    g_w3[i] = __float2half(v);
}

// ---------------- launch-level zero ----------------
__global__ void k_zero0() {
    int i = blockIdx.x * blockDim.x + threadIdx.x;
    if (i < NN * NDIM) g_agg[i] = 0.f;
    if (i < 256) g_stats[i] = 0.f;
    if (i < NG * NDIM) g_gsum[i] = 0.f;
    if (i < NG) g_gcnt[i] = 0.f;
}

// ---------------- P = nf @ [W_dst | W_src] via fp16 mma ----------------
// grid (ceil(NN/64), 2): y = which half (0: W rows 0..63 -> P cols 0..127;
//                                        1: W rows 64..127 -> P cols 128..255).
// Tile M64 x N128, K=64 (4 k-steps). 256 threads, 8 warps (wm = w&3, wn = w>>2).
__global__ void k_pgemm16(const float* __restrict__ convW, int l) {
    __shared__ __half Ah[64 * KP2];
    __shared__ __half Bh[128 * KP2];
    int tid = threadIdx.x;
    int m0 = blockIdx.x * 64;
    int half_id = blockIdx.y;

    // A: nf rows m0..m0+63, 64 dims (k fast -> coalesced)
    for (int idx = tid; idx < 64 * 64; idx += 256) {
        int r = idx >> 6, k = idx & 63;
        int v = m0 + r;
        Ah[r * KP2 + k] = __float2half((v < NN) ? g_nf[v * 64 + k] : 0.f);
    }
    // B: Bh[n][k] = W[half*64 + k][n]  (n fast -> coalesced over convW row)
    const float* W = convW + (l * 169 + half_id * 64) * 128;
    for (int idx = tid; idx < 128 * 64; idx += 256) {
        int k = idx >> 7, n = idx & 127;
        Bh[n * KP2 + k] = __float2half(W[k * 128 + n]);
    }
    __syncthreads();

    int w = tid >> 5, lane = tid & 31;
    int wm = w & 3, wn = w >> 2;
    int g = lane >> 2, tq = lane & 3;
    float acc[32];
#pragma unroll
    for (int i = 0; i < 32; i++) acc[i] = 0.f;
    int ar0 = wm * 16 + g;

#pragma unroll
    for (int ks = 0; ks < 4; ks++) {
        int kb = ks * 16 + tq * 2;
        uint32_t a0 = *(const uint32_t*)&Ah[ar0 * KP2 + kb];
        uint32_t a1 = *(const uint32_t*)&Ah[(ar0 + 8) * KP2 + kb];
        uint32_t a2 = *(const uint32_t*)&Ah[ar0 * KP2 + kb + 8];
        uint32_t a3 = *(const uint32_t*)&Ah[(ar0 + 8) * KP2 + kb + 8];
#pragma unroll
        for (int ns = 0; ns < 8; ns++) {
            int bn = wn * 64 + ns * 8 + g;
            uint32_t b0 = *(const uint32_t*)&Bh[bn * KP2 + kb];
            uint32_t b1 = *(const uint32_t*)&Bh[bn * KP2 + kb + 8];
            float* c = acc + ns * 4;
            MMA_F16(c[0], c[1], c[2], c[3], a0, a1, a2, a3, b0, b1);
        }
    }

    int row0 = m0 + wm * 16 + g;
#pragma unroll
    for (int ns = 0; ns < 8; ns++) {
        int col = half_id * 128 + wn * 64 + ns * 8 + tq * 2;
        if (row0 < NN)
            ((__half2*)g_P)[((size_t)row0 * 256 + col) >> 1] =
                __floats2half2_rn(acc[ns * 4 + 0], acc[ns * 4 + 1]);
        if (row0 + 8 < NN)
            ((__half2*)g_P)[((size_t)(row0 + 8) * 256 + col) >> 1] =
                __floats2half2_rn(acc[ns * 4 + 2], acc[ns * 4 + 3]);
    }
}

// ---------------- fused: z = ea@W3 + P1[dst] + P2[src] (fp16 mma) + z store + BN stats ----------------
// Tile M64 x N128, 256 threads (8 warps): wm = w & 3, wn = w >> 2. Conv bias cancels in BN.
__global__ void k_ewfused16(const float* __restrict__ ea,
                            const int* __restrict__ eidx, int l) {
    __shared__ __half Ah[64 * KPAD];
    __shared__ __half Bh[128 * KPAD];
    __shared__ float sred[256];
    int tid = threadIdx.x;
    int m0 = blockIdx.x * 64;

    sred[tid] = 0.f;
    for (int idx = tid; idx < 64 * KPAD; idx += 256) {
        int r = idx / KPAD, k = idx - r * KPAD;
        float v = (k < EDIM) ? ea[(size_t)(m0 + r) * EDIM + k] : 0.f;
        Ah[idx] = __float2half(v);
    }
    const __half* w3 = g_w3 + l * 128 * KPAD;
    for (int idx = tid; idx < 128 * KPAD; idx += 256) {
        Bh[idx] = w3[idx];
    }
    __syncthreads();

    int w = tid >> 5, lane = tid & 31;
    int wm = w & 3, wn = w >> 2;
    int g = lane >> 2, tq = lane & 3;
    float acc[32];
#pragma unroll
    for (int i = 0; i < 32; i++) acc[i] = 0.f;
    int ar0 = wm * 16 + g;

#pragma unroll
    for (int ks = 0; ks < 3; ks++) {
        int kb = ks * 16 + tq * 2;
        uint32_t a0 = *(const uint32_t*)&Ah[ar0 * KPAD + kb];
        uint32_t a1 = *(const uint32_t*)&Ah[(ar0 + 8) * KPAD + kb];
        uint32_t a2 = *(const uint32_t*)&Ah[ar0 * KPAD + kb + 8];
        uint32_t a3 = *(const uint32_t*)&Ah[(ar0 + 8) * KPAD + kb + 8];
#pragma unroll
        for (int ns = 0; ns < 8; ns++) {
            int bn = wn * 64 + ns * 8 + g;
            uint32_t b0 = *(const uint32_t*)&Bh[bn * KPAD + kb];
            uint32_t b1 = *(const uint32_t*)&Bh[bn * KPAD + kb + 8];
            float* c = acc + ns * 4;
            MMA_F16(c[0], c[1], c[2], c[3], a0, a1, a2, a3, b0, b1);
        }
    }

    // ---- epilogue: gather P (fp16, L2-resident), write z fp16, reduce BN stats ----
    int r0 = wm * 16 + g, r1 = r0 + 8;
    int d0 = eidx[NE + m0 + r0], s0 = eidx[m0 + r0];
    int d1 = eidx[NE + m0 + r1], s1 = eidx[m0 + r1];
#pragma unroll
    for (int ns = 0; ns < 8; ns++) {
        int col = wn * 64 + ns * 8 + tq * 2;
        float2 pd0 = __half22float2(*(const __half2*)&g_P[(size_t)d0 * 256 + col]);
        float2 ps0 = __half22float2(*(const __half2*)&g_P[(size_t)s0 * 256 + 128 + col]);
        float2 pd1 = __half22float2(*(const __half2*)&g_P[(size_t)d1 * 256 + col]);
        float2 ps1 = __half22float2(*(const __half2*)&g_P[(size_t)s1 * 256 + 128 + col]);
        float z00 = acc[ns * 4 + 0] + pd0.x + ps0.x;
        float z01 = acc[ns * 4 + 1] + pd0.y + ps0.y;
        float z10 = acc[ns * 4 + 2] + pd1.x + ps1.x;
        float z11 = acc[ns * 4 + 3] + pd1.y + ps1.y;
        ((__half2*)g_z)[((size_t)(m0 + r0) * 128 + col) >> 1] = __floats2half2_rn(z00, z01);
        ((__half2*)g_z)[((size_t)(m0 + r1) * 128 + col) >> 1] = __floats2half2_rn(z10, z11);
        acc[ns * 4 + 0] = z00 + z10;
        acc[ns * 4 + 1] = z01 + z11;
        acc[ns * 4 + 2] = z00 * z00 + z10 * z10;
        acc[ns * 4 + 3] = z01 * z01 + z11 * z11;
    }
    // reduce across g (lane bits 2..4); tq preserved
#pragma unroll
    for (int off = 4; off <= 16; off <<= 1) {
#pragma unroll
        for (int i = 0; i < 32; i++)
            acc[i] += __shfl_xor_sync(0xffffffff, acc[i], off);
    }
    if (g == 0) {
#pragma unroll
        for (int ns = 0; ns < 8; ns++) {
            int col = wn * 64 + ns * 8 + tq * 2;
            atomicAdd(&sred[col],           acc[ns * 4 + 0]);
            atomicAdd(&sred[col + 1],       acc[ns * 4 + 1]);
            atomicAdd(&sred[128 + col],     acc[ns * 4 + 2]);
            atomicAdd(&sred[129 + col],     acc[ns * 4 + 3]);
        }
    }
    __syncthreads();
    atomicAdd(&g_stats[tid], sred[tid]);
}

// ---------------- finalize BN stats -> scale/bias (self-zero stats) ----------------
__global__ void k_stats(const float* __restrict__ bnG,
                        const float* __restrict__ bnB, int l) {
    int c = threadIdx.x;  // 0..127
    float inv = 1.f / (float)NE;
    float mu = g_stats[c] * inv;
    float var = g_stats[128 + c] * inv - mu * mu;
    float sc = rsqrtf(var + EPSV) * bnG[l * 128 + c];
    g_sb[c] = sc;
    g_sb[128 + c] = bnB[l * 128 + c] - mu * sc;
    g_stats[c] = 0.f;
    g_stats[128 + c] = 0.f;
}

// ---------------- apply: read z, BN + gate + scatter-add (no gathers) ----------------
__global__ void k_apply(const int* __restrict__ eidx) {
    __shared__ float sb[256];
    __shared__ int sdst[256];
    int tid = threadIdx.x;
    sb[tid] = g_sb[tid];
    int e0 = blockIdx.x * 256;
    sdst[tid] = eidx[NE + e0 + tid];
    __syncthreads();
    int j = (tid & 31) * 2;   // column pair 0..62
    int es = tid >> 5;        // 0..7
    float sc1a = sb[j],       sc1b = sb[j + 1];
    float bi1a = sb[128 + j], bi1b = sb[129 + j];
    float sc2a = sb[64 + j],  sc2b = sb[65 + j];
    float bi2a = sb[192 + j], bi2b = sb[193 + j];
#pragma unroll 4
    for (int i = 0; i < 32; i++) {
        int er = 8 * i + es;
        size_t e = (size_t)(e0 + er);
        int d = sdst[er];
        __half2 a = *((const __half2*)&g_z[e * 128 + j]);
        __half2 b = *((const __half2*)&g_z[e * 128 + 64 + j]);
        float z1a = __low2float(a) * sc1a + bi1a;
        float z1b = __high2float(a) * sc1b + bi1b;
        float z2a = __low2float(b) * sc2a + bi2a;
        float z2b = __high2float(b) * sc2b + bi2b;
        float ma = sig_f(z1a) * sp_f(z2a);
        float mb = sig_f(z1b) * sp_f(z2b);
        atomicAdd(&g_agg[(size_t)d * 64 + j], ma);
        atomicAdd(&g_agg[(size_t)d * 64 + j + 1], mb);
    }
}

// ---------------- node update: softplus(LN(agg) + nf); self-zero agg ----------------
__global__ void k_node(const float* __restrict__ lnG,
                       const float* __restrict__ lnB, int l) {
    int v = blockIdx.x * 4 + (threadIdx.x >> 5);
    int lane = threadIdx.x & 31;
    if (v >= NN) return;
    float a0 = g_agg[v * 64 + lane];
    float a1 = g_agg[v * 64 + 32 + lane];
    g_agg[v * 64 + lane] = 0.f;
    g_agg[v * 64 + 32 + lane] = 0.f;
    float s = a0 + a1;
    float sq = a0 * a0 + a1 * a1;
#pragma unroll
    for (int o = 16; o > 0; o >>= 1) {
        s  += __shfl_xor_sync(0xffffffff, s, o);
        sq += __shfl_xor_sync(0xffffffff, sq, o);
    }
    float mu = s * (1.f / 64.f);
    float var = sq * (1.f / 64.f) - mu * mu;
    float rs = rsqrtf(var + EPSV);
    float l0 = (a0 - mu) * rs * lnG[l * 64 + lane] + lnB[l * 64 + lane];
    float l1 = (a1 - mu) * rs * lnG[l * 64 + 32 + lane] + lnB[l * 64 + 32 + lane];
    g_nf[v * 64 + lane]      = sp_f(l0 + g_nf[v * 64 + lane]);
    g_nf[v * 64 + 32 + lane] = sp_f(l1 + g_nf[v * 64 + 32 + lane]);
}

// ---------------- pooling ----------------
__global__ void k_pool(const int* __restrict__ batch) {
    int tid = blockIdx.x * blockDim.x + threadIdx.x;
    int v = tid >> 6;
    int c = tid & 63;
    if (v >= NN) return;
    int g = batch[v];
    atomicAdd(&g_gsum[g * 64 + c], g_nf[v * 64 + c]);
    if (c == 0) atomicAdd(&g_gcnt[g], 1.f);
}

// ---------------- final MLP head (300 graphs) ----------------
__global__ void k_mlp(const float* __restrict__ fc1W, const float* __restrict__ fc1B,
                      const float* __restrict__ fcsW, const float* __restrict__ fcsB,
                      const float* __restrict__ foW, const float* __restrict__ foB,
                      float* __restrict__ out) {
    int g = blockIdx.x;
    int c = threadIdx.x;  // 0..127
    __shared__ float s[64];
    __shared__ float h[128];
    __shared__ float red[128];

    if (c < 64) {
        float cnt = g_gcnt[g];
        s[c] = g_gsum[g * 64 + c] / fmaxf(cnt, 1.f);
    }
    __syncthreads();
    float acc = fc1B[c];
#pragma unroll 4
    for (int k = 0; k < 64; k++) acc += s[k] * fc1W[k * 128 + c];
    h[c] = sp_f(acc);
    __syncthreads();
    for (int lh = 0; lh < 3; lh++) {
        float a = fcsB[lh * 128 + c];
#pragma unroll 4
        for (int k = 0; k < 128; k++) a += h[k] * fcsW[(lh * 128 + k) * 128 + c];
        __syncthreads();
        h[c] = sp_f(a);
        __syncthreads();
    }
    red[c] = h[c] * foW[c];
    __syncthreads();
#pragma unroll
    for (int o = 64; o > 0; o >>= 1) {
        if (c < o) red[c] += red[c + o];
        __syncthreads();
    }
    if (c == 0) out[g] = red[0] + foB[0];
}

// ---------------- launch ----------------
extern "C" void kernel_launch(void* const* d_in, const int* in_sizes, int n_in,
                              void* d_out, int out_size) {
    const float* x        = (const float*)d_in[0];
    const float* edge_attr= (const float*)d_in[1];
    const float* embW     = (const float*)d_in[2];
    const float* embB     = (const float*)d_in[3];
    const float* convW    = (const float*)d_in[4];
    const float* bnG      = (const float*)d_in[6];
    const float* bnB      = (const float*)d_in[7];
    const float* lnG      = (const float*)d_in[8];
    const float* lnB      = (const float*)d_in[9];
    const float* fc1W     = (const float*)d_in[10];
    const float* fc1B     = (const float*)d_in[11];
    const float* fcsW     = (const float*)d_in[12];
    const float* fcsB     = (const float*)d_in[13];
    const float* foW      = (const float*)d_in[14];
    const float* foB      = (const float*)d_in[15];
    const int*   eidx     = (const int*)d_in[16];
    const int*   batch    = (const int*)d_in[17];
    float* out = (float*)d_out;

    k_zero0<<<(NN * NDIM + 255) / 256, 256>>>();
    k_embed<<<(NN + 7) / 8, 64>>>(x, embW, embB);
    k_prepw<<<(NCONV * 128 * KPAD + 255) / 256, 256>>>(convW);

    for (int l = 0; l < NCONV; l++) {
        k_pgemm16<<<dim3((NN + 63) / 64, 2), 256>>>(convW, l);
        k_ewfused16<<<NE / 64, 256>>>(edge_attr, eidx, l);
        k_stats<<<1, 128>>>(bnG, bnB, l);
        k_apply<<<NE / 256, 256>>>(eidx);
        k_node<<<(NN + 3) / 4, 128>>>(lnG, lnB, l);
    }

    k_pool<<<(NN * 64 + 255) / 256, 256>>>(batch);
    k_mlp<<<NG, 128>>>(fc1W, fc1B, fcsW, fcsB, foW, foB, out);
}

// round 13
// speedup vs baseline: 1.2868x; 1.0359x over previous
#include <cuda_runtime.h>
#include <cuda_fp16.h>
#include <stdint.h>
#include <math.h>

#define NN 30000
#define NE 480000
#define NG 300
#define NDIM 64
#define EDIM 41
#define NCONV 6
#define EPSV 1e-5f
#define KPAD 48
#define KP2 72   // pgemm16 K padding

// ---- scratch (static device globals; no runtime allocation) ----
__device__ float g_nf[NN * NDIM];            // node features fp32 (7.7 MB)
__device__ __half g_P[NN * 256];             // [P1 | P2] per node, fp16 (15.4 MB, L2-resident)
__device__ __half g_z[(size_t)NE * 128];     // per-layer pre-BN z (123 MB)
__device__ __half g_w3[NCONV * 128 * KPAD];  // W3 fp16, [l][c][k]
__device__ __half g_ea16[(size_t)NE * KPAD]; // edge_attr fp16 padded (46 MB)
__device__ float g_agg[NN * NDIM];
__device__ float g_stats[256];               // sum[0:128], sumsq[128:256]
__device__ float g_sb[256];                  // BN scale[0:128], bias[128:256]
__device__ float g_gsum[NG * NDIM];
__device__ float g_gcnt[NG];

__device__ __forceinline__ float sp_f(float x) {
    return x > 20.f ? x : log1pf(__expf(x));
}
__device__ __forceinline__ float sig_f(float x) {
    return 1.f / (1.f + __expf(-x));
}

#define MMA_F16(c0,c1,c2,c3,a0,a1,a2,a3,b0,b1) \
  asm volatile("mma.sync.aligned.m16n8k16.row.col.f32.f16.f16.f32 " \
      "{%0,%1,%2,%3}, {%4,%5,%6,%7}, {%8,%9}, {%0,%1,%2,%3};" \
      : "+f"(c0),"+f"(c1),"+f"(c2),"+f"(c3) \
      : "r"(a0),"r"(a1),"r"(a2),"r"(a3),"r"(b0),"r"(b1))

// ---------------- embed: nf = x @ embW + embB ----------------
__global__ void k_embed(const float* __restrict__ x,
                        const float* __restrict__ embW,
                        const float* __restrict__ embB) {
    int c = threadIdx.x;           // 0..63
    float w[92];
#pragma unroll
    for (int k = 0; k < 92; k++) w[k] = embW[k * 64 + c];
    float b = embB[c];

    __shared__ float xs[8][92];
    int v0 = blockIdx.x * 8;
    for (int i = threadIdx.x; i < 8 * 92; i += 64) {
        int n = i / 92, k = i % 92;
        int v = v0 + n;
        xs[n][k] = (v < NN) ? x[v * 92 + k] : 0.f;
    }
    __syncthreads();
#pragma unroll 2
    for (int n = 0; n < 8; n++) {
        int v = v0 + n;
        if (v >= NN) break;
        float acc = b;
#pragma unroll
        for (int k = 0; k < 92; k++) acc += xs[n][k] * w[k];
        g_nf[v * 64 + c] = acc;
    }
}

// ---------------- prep: W3 -> fp16 [l][c][k]; ea -> fp16 [e][KPAD] ----------------
__global__ void k_prepw(const float* __restrict__ convW) {
    int i = blockIdx.x * 256 + threadIdx.x;
    if (i >= NCONV * 128 * KPAD) return;
    int n = i / KPAD, k = i - n * KPAD;
    int l = n >> 7, c = n & 127;
    float v = (k < EDIM) ? convW[(l * 169 + 128 + k) * 128 + c] : 0.f;
    g_w3[i] = __float2half(v);
}

__global__ void k_prepea(const float* __restrict__ ea) {
    size_t i = (size_t)blockIdx.x * 256 + threadIdx.x;
    if (i >= (size_t)NE * KPAD) return;
    size_t e = i / KPAD;
    int k = (int)(i - e * KPAD);
    g_ea16[i] = __float2half((k < EDIM) ? ea[e * EDIM + k] : 0.f);
}

// ---------------- launch-level zero ----------------
__global__ void k_zero0() {
    int i = blockIdx.x * blockDim.x + threadIdx.x;
    if (i < NN * NDIM) g_agg[i] = 0.f;
    if (i < 256) g_stats[i] = 0.f;
    if (i < NG * NDIM) g_gsum[i] = 0.f;
    if (i < NG) g_gcnt[i] = 0.f;
}

// ---------------- P = nf @ [W_dst | W_src] via fp16 mma ----------------
__global__ void k_pgemm16(const float* __restrict__ convW, int l) {
    __shared__ __half Ah[64 * KP2];
    __shared__ __half Bh[128 * KP2];
    int tid = threadIdx.x;
    int m0 = blockIdx.x * 64;
    int half_id = blockIdx.y;

    for (int idx = tid; idx < 64 * 64; idx += 256) {
        int r = idx >> 6, k = idx & 63;
        int v = m0 + r;
        Ah[r * KP2 + k] = __float2half((v < NN) ? g_nf[v * 64 + k] : 0.f);
    }
    const float* W = convW + (l * 169 + half_id * 64) * 128;
    for (int idx = tid; idx < 128 * 64; idx += 256) {
        int k = idx >> 7, n = idx & 127;
        Bh[n * KP2 + k] = __float2half(W[k * 128 + n]);
    }
    __syncthreads();

    int w = tid >> 5, lane = tid & 31;
    int wm = w & 3, wn = w >> 2;
    int g = lane >> 2, tq = lane & 3;
    float acc[32];
#pragma unroll
    for (int i = 0; i < 32; i++) acc[i] = 0.f;
    int ar0 = wm * 16 + g;

#pragma unroll
    for (int ks = 0; ks < 4; ks++) {
        int kb = ks * 16 + tq * 2;
        uint32_t a0 = *(const uint32_t*)&Ah[ar0 * KP2 + kb];
        uint32_t a1 = *(const uint32_t*)&Ah[(ar0 + 8) * KP2 + kb];
        uint32_t a2 = *(const uint32_t*)&Ah[ar0 * KP2 + kb + 8];
        uint32_t a3 = *(const uint32_t*)&Ah[(ar0 + 8) * KP2 + kb + 8];
#pragma unroll
        for (int ns = 0; ns < 8; ns++) {
            int bn = wn * 64 + ns * 8 + g;
            uint32_t b0 = *(const uint32_t*)&Bh[bn * KP2 + kb];
            uint32_t b1 = *(const uint32_t*)&Bh[bn * KP2 + kb + 8];
            float* c = acc + ns * 4;
            MMA_F16(c[0], c[1], c[2], c[3], a0, a1, a2, a3, b0, b1);
        }
    }

    int row0 = m0 + wm * 16 + g;
#pragma unroll
    for (int ns = 0; ns < 8; ns++) {
        int col = half_id * 128 + wn * 64 + ns * 8 + tq * 2;
        if (row0 < NN)
            ((__half2*)g_P)[((size_t)row0 * 256 + col) >> 1] =
                __floats2half2_rn(acc[ns * 4 + 0], acc[ns * 4 + 1]);
        if (row0 + 8 < NN)
            ((__half2*)g_P)[((size_t)(row0 + 8) * 256 + col) >> 1] =
                __floats2half2_rn(acc[ns * 4 + 2], acc[ns * 4 + 3]);
    }
}

// ---------------- fused: z = ea@W3 + P1[dst] + P2[src] + z store + BN stats ----------------
// Tile M64 x N128. P gathers PREFETCHED into registers before the MMA loop so
// their L2 latency hides under smem fill + MMA work. Conv bias cancels in BN.
__global__ void k_ewfused16(const int* __restrict__ eidx, int l) {
    __shared__ __half Ah[64 * KPAD];
    __shared__ __half Bh[128 * KPAD];
    __shared__ float sred[256];
    int tid = threadIdx.x;
    int m0 = blockIdx.x * 64;

    int w = tid >> 5, lane = tid & 31;
    int wm = w & 3, wn = w >> 2;
    int g = lane >> 2, tq = lane & 3;

    // ---- prefetch indices + P gathers (independent of MMA) ----
    int r0 = wm * 16 + g, r1 = r0 + 8;
    int d0 = eidx[NE + m0 + r0], s0 = eidx[m0 + r0];
    int d1 = eidx[NE + m0 + r1], s1 = eidx[m0 + r1];
    __half2 pd0[8], ps0[8], pd1[8], ps1[8];
#pragma unroll
    for (int ns = 0; ns < 8; ns++) {
        int col = wn * 64 + ns * 8 + tq * 2;
        pd0[ns] = *(const __half2*)&g_P[(size_t)d0 * 256 + col];
        ps0[ns] = *(const __half2*)&g_P[(size_t)s0 * 256 + 128 + col];
        pd1[ns] = *(const __half2*)&g_P[(size_t)d1 * 256 + col];
        ps1[ns] = *(const __half2*)&g_P[(size_t)s1 * 256 + 128 + col];
    }

    sred[tid] = 0.f;
    // A fill: straight uint32 copy from prepadded fp16 ea
    const uint32_t* easrc = (const uint32_t*)(g_ea16 + (size_t)m0 * KPAD);
    for (int idx = tid; idx < 64 * KPAD / 2; idx += 256)
        ((uint32_t*)Ah)[idx] = easrc[idx];
    const uint32_t* w3 = (const uint32_t*)(g_w3 + l * 128 * KPAD);
    for (int idx = tid; idx < 128 * KPAD / 2; idx += 256)
        ((uint32_t*)Bh)[idx] = w3[idx];
    __syncthreads();

    float acc[32];
#pragma unroll
    for (int i = 0; i < 32; i++) acc[i] = 0.f;
    int ar0 = wm * 16 + g;

#pragma unroll
    for (int ks = 0; ks < 3; ks++) {
        int kb = ks * 16 + tq * 2;
        uint32_t a0 = *(const uint32_t*)&Ah[ar0 * KPAD + kb];
        uint32_t a1 = *(const uint32_t*)&Ah[(ar0 + 8) * KPAD + kb];
        uint32_t a2 = *(const uint32_t*)&Ah[ar0 * KPAD + kb + 8];
        uint32_t a3 = *(const uint32_t*)&Ah[(ar0 + 8) * KPAD + kb + 8];
#pragma unroll
        for (int ns = 0; ns < 8; ns++) {
            int bn = wn * 64 + ns * 8 + g;
            uint32_t b0 = *(const uint32_t*)&Bh[bn * KPAD + kb];
            uint32_t b1 = *(const uint32_t*)&Bh[bn * KPAD + kb + 8];
            float* c = acc + ns * 4;
            MMA_F16(c[0], c[1], c[2], c[3], a0, a1, a2, a3, b0, b1);
        }
    }

    // ---- epilogue: combine with prefetched P, write z fp16, reduce BN stats ----
#pragma unroll
    for (int ns = 0; ns < 8; ns++) {
        int col = wn * 64 + ns * 8 + tq * 2;
        float2 fd0 = __half22float2(pd0[ns]);
        float2 fs0 = __half22float2(ps0[ns]);
        float2 fd1 = __half22float2(pd1[ns]);
        float2 fs1 = __half22float2(ps1[ns]);
        float z00 = acc[ns * 4 + 0] + fd0.x + fs0.x;
        float z01 = acc[ns * 4 + 1] + fd0.y + fs0.y;
        float z10 = acc[ns * 4 + 2] + fd1.x + fs1.x;
        float z11 = acc[ns * 4 + 3] + fd1.y + fs1.y;
        ((__half2*)g_z)[((size_t)(m0 + r0) * 128 + col) >> 1] = __floats2half2_rn(z00, z01);
        ((__half2*)g_z)[((size_t)(m0 + r1) * 128 + col) >> 1] = __floats2half2_rn(z10, z11);
        acc[ns * 4 + 0] = z00 + z10;
        acc[ns * 4 + 1] = z01 + z11;
        acc[ns * 4 + 2] = z00 * z00 + z10 * z10;
        acc[ns * 4 + 3] = z01 * z01 + z11 * z11;
    }
    // reduce across g (lane bits 2..4); tq preserved
#pragma unroll
    for (int off = 4; off <= 16; off <<= 1) {
#pragma unroll
        for (int i = 0; i < 32; i++)
            acc[i] += __shfl_xor_sync(0xffffffff, acc[i], off);
    }
    if (g == 0) {
#pragma unroll
        for (int ns = 0; ns < 8; ns++) {
            int col = wn * 64 + ns * 8 + tq * 2;
            atomicAdd(&sred[col],           acc[ns * 4 + 0]);
            atomicAdd(&sred[col + 1],       acc[ns * 4 + 1]);
            atomicAdd(&sred[128 + col],     acc[ns * 4 + 2]);
            atomicAdd(&sred[129 + col],     acc[ns * 4 + 3]);
        }
    }
    __syncthreads();
    atomicAdd(&g_stats[tid], sred[tid]);
}

// ---------------- finalize BN stats -> scale/bias (self-zero stats) ----------------
__global__ void k_stats(const float* __restrict__ bnG,
                        const float* __restrict__ bnB, int l) {
    int c = threadIdx.x;  // 0..127
    float inv = 1.f / (float)NE;
    float mu = g_stats[c] * inv;
    float var = g_stats[128 + c] * inv - mu * mu;
    float sc = rsqrtf(var + EPSV) * bnG[l * 128 + c];
    g_sb[c] = sc;
    g_sb[128 + c] = bnB[l * 128 + c] - mu * sc;
    g_stats[c] = 0.f;
    g_stats[128 + c] = 0.f;
}

// ---------------- apply: read z, BN + gate + scatter-add (no gathers) ----------------
__global__ void k_apply(const int* __restrict__ eidx) {
    __shared__ float sb[256];
    __shared__ int sdst[256];
    int tid = threadIdx.x;
    sb[tid] = g_sb[tid];
    int e0 = blockIdx.x * 256;
    sdst[tid] = eidx[NE + e0 + tid];
    __syncthreads();
    int j = (tid & 31) * 2;   // column pair 0..62
    int es = tid >> 5;        // 0..7
    float sc1a = sb[j],       sc1b = sb[j + 1];
    float bi1a = sb[128 + j], bi1b = sb[129 + j];
    float sc2a = sb[64 + j],  sc2b = sb[65 + j];
    float bi2a = sb[192 + j], bi2b = sb[193 + j];
#pragma unroll 4
    for (int i = 0; i < 32; i++) {
        int er = 8 * i + es;
        size_t e = (size_t)(e0 + er);
        int d = sdst[er];
        __half2 a = *((const __half2*)&g_z[e * 128 + j]);
        __half2 b = *((const __half2*)&g_z[e * 128 + 64 + j]);
        float z1a = __low2float(a) * sc1a + bi1a;
        float z1b = __high2float(a) * sc1b + bi1b;
        float z2a = __low2float(b) * sc2a + bi2a;
        float z2b = __high2float(b) * sc2b + bi2b;
        float ma = sig_f(z1a) * sp_f(z2a);
        float mb = sig_f(z1b) * sp_f(z2b);
        atomicAdd(&g_agg[(size_t)d * 64 + j], ma);
        atomicAdd(&g_agg[(size_t)d * 64 + j + 1], mb);
    }
}

// ---------------- node update: softplus(LN(agg) + nf); self-zero agg ----------------
__global__ void k_node(const float* __restrict__ lnG,
                       const float* __restrict__ lnB, int l) {
    int v = blockIdx.x * 4 + (threadIdx.x >> 5);
    int lane = threadIdx.x & 31;
    if (v >= NN) return;
    float a0 = g_agg[v * 64 + lane];
    float a1 = g_agg[v * 64 + 32 + lane];
    g_agg[v * 64 + lane] = 0.f;
    g_agg[v * 64 + 32 + lane] = 0.f;
    float s = a0 + a1;
    float sq = a0 * a0 + a1 * a1;
#pragma unroll
    for (int o = 16; o > 0; o >>= 1) {
        s  += __shfl_xor_sync(0xffffffff, s, o);
        sq += __shfl_xor_sync(0xffffffff, sq, o);
    }
    float mu = s * (1.f / 64.f);
    float var = sq * (1.f / 64.f) - mu * mu;
    float rs = rsqrtf(var + EPSV);
    float l0 = (a0 - mu) * rs * lnG[l * 64 + lane] + lnB[l * 64 + lane];
    float l1 = (a1 - mu) * rs * lnG[l * 64 + 32 + lane] + lnB[l * 64 + 32 + lane];
    g_nf[v * 64 + lane]      = sp_f(l0 + g_nf[v * 64 + lane]);
    g_nf[v * 64 + 32 + lane] = sp_f(l1 + g_nf[v * 64 + 32 + lane]);
}

// ---------------- pooling ----------------
__global__ void k_pool(const int* __restrict__ batch) {
    int tid = blockIdx.x * blockDim.x + threadIdx.x;
    int v = tid >> 6;
    int c = tid & 63;
    if (v >= NN) return;
    int g = batch[v];
    atomicAdd(&g_gsum[g * 64 + c], g_nf[v * 64 + c]);
    if (c == 0) atomicAdd(&g_gcnt[g], 1.f);
}

// ---------------- final MLP head (300 graphs) ----------------
__global__ void k_mlp(const float* __restrict__ fc1W, const float* __restrict__ fc1B,
                      const float* __restrict__ fcsW, const float* __restrict__ fcsB,
                      const float* __restrict__ foW, const float* __restrict__ foB,
                      float* __restrict__ out) {
    int g = blockIdx.x;
    int c = threadIdx.x;  // 0..127
    __shared__ float s[64];
    __shared__ float h[128];
    __shared__ float red[128];

    if (c < 64) {
        float cnt = g_gcnt[g];
        s[c] = g_gsum[g * 64 + c] / fmaxf(cnt, 1.f);
    }
    __syncthreads();
    float acc = fc1B[c];
#pragma unroll 4
    for (int k = 0; k < 64; k++) acc += s[k] * fc1W[k * 128 + c];
    h[c] = sp_f(acc);
    __syncthreads();
    for (int lh = 0; lh < 3; lh++) {
        float a = fcsB[lh * 128 + c];
#pragma unroll 4
        for (int k = 0; k < 128; k++) a += h[k] * fcsW[(lh * 128 + k) * 128 + c];
        __syncthreads();
        h[c] = sp_f(a);
        __syncthreads();
    }
    red[c] = h[c] * foW[c];
    __syncthreads();
#pragma unroll
    for (int o = 64; o > 0; o >>= 1) {
        if (c < o) red[c] += red[c + o];
        __syncthreads();
    }
    if (c == 0) out[g] = red[0] + foB[0];
}

// ---------------- launch ----------------
extern "C" void kernel_launch(void* const* d_in, const int* in_sizes, int n_in,
                              void* d_out, int out_size) {
    const float* x        = (const float*)d_in[0];
    const float* edge_attr= (const float*)d_in[1];
    const float* embW     = (const float*)d_in[2];
    const float* embB     = (const float*)d_in[3];
    const float* convW    = (const float*)d_in[4];
    const float* bnG      = (const float*)d_in[6];
    const float* bnB      = (const float*)d_in[7];
    const float* lnG      = (const float*)d_in[8];
    const float* lnB      = (const float*)d_in[9];
    const float* fc1W     = (const float*)d_in[10];
    const float* fc1B     = (const float*)d_in[11];
    const float* fcsW     = (const float*)d_in[12];
    const float* fcsB     = (const float*)d_in[13];
    const float* foW      = (const float*)d_in[14];
    const float* foB      = (const float*)d_in[15];
    const int*   eidx     = (const int*)d_in[16];
    const int*   batch    = (const int*)d_in[17];
    float* out = (float*)d_out;

    k_zero0<<<(NN * NDIM + 255) / 256, 256>>>();
    k_embed<<<(NN + 7) / 8, 64>>>(x, embW, embB);
    k_prepw<<<(NCONV * 128 * KPAD + 255) / 256, 256>>>(convW);
    k_prepea<<<(int)(((size_t)NE * KPAD + 255) / 256), 256>>>(edge_attr);

    for (int l = 0; l < NCONV; l++) {
        k_pgemm16<<<dim3((NN + 63) / 64, 2), 256>>>(convW, l);
        k_ewfused16<<<NE / 64, 256>>>(eidx, l);
        k_stats<<<1, 128>>>(bnG, bnB, l);
        k_apply<<<NE / 256, 256>>>(eidx);
        k_node<<<(NN + 3) / 4, 128>>>(lnG, lnB, l);
    }

    k_pool<<<(NN * 64 + 255) / 256, 256>>>(batch);
    k_mlp<<<NG, 128>>>(fc1W, fc1B, fcsW, fcsB, foW, foB, out);
}